// round 1
// baseline (speedup 1.0000x reference)
#include <cuda_runtime.h>
#include <cuda_bf16.h>

#define NF 2048
#define NF4 (NF / 4)          // 512 float4 per row
#define EPS 1e-6f

// Scratch (allocation-free rule: __device__ globals)
__device__ __align__(16) float g_sum[NF];
__device__ __align__(16) float g_sumsq[NF];
__device__ __align__(16) float g_mean[NF];
__device__ __align__(16) float g_istd[NF];

__global__ void zero_kernel() {
    int i = blockIdx.x * blockDim.x + threadIdx.x;
    if (i < NF) {
        g_sum[i] = 0.0f;
        g_sumsq[i] = 0.0f;
    }
}

// grid: (NF4/256, numRowChunks); each thread owns 4 adjacent columns, walks
// rowsPerChunk rows, then atomically merges 8 partials.
__global__ void reduce_kernel(const float* __restrict__ x, int rows, int rowsPerChunk) {
    int col4 = blockIdx.x * blockDim.x + threadIdx.x;       // 0..NF4-1
    int r0 = blockIdx.y * rowsPerChunk;
    int r1 = min(r0 + rowsPerChunk, rows);

    const float4* xp = reinterpret_cast<const float4*>(x);
    float sx = 0.f, sy = 0.f, sz = 0.f, sw = 0.f;
    float qx = 0.f, qy = 0.f, qz = 0.f, qw = 0.f;

    for (int r = r0; r < r1; ++r) {
        float4 v = xp[(size_t)r * NF4 + col4];
        sx += v.x; sy += v.y; sz += v.z; sw += v.w;
        qx += v.x * v.x; qy += v.y * v.y; qz += v.z * v.z; qw += v.w * v.w;
    }

    int c = col4 * 4;
    atomicAdd(&g_sum[c + 0], sx);
    atomicAdd(&g_sum[c + 1], sy);
    atomicAdd(&g_sum[c + 2], sz);
    atomicAdd(&g_sum[c + 3], sw);
    atomicAdd(&g_sumsq[c + 0], qx);
    atomicAdd(&g_sumsq[c + 1], qy);
    atomicAdd(&g_sumsq[c + 2], qz);
    atomicAdd(&g_sumsq[c + 3], qw);
}

__global__ void stats_kernel(int rows) {
    int c = blockIdx.x * blockDim.x + threadIdx.x;
    if (c < NF) {
        float n = (float)rows;
        float mean = g_sum[c] / n;
        float var = (g_sumsq[c] - n * mean * mean) / (n - 1.0f);
        g_mean[c] = mean;
        g_istd[c] = rsqrtf(var + EPS);
    }
}

__global__ void normalize_kernel(const float* __restrict__ x,
                                 float* __restrict__ out, size_t n4) {
    size_t i = (size_t)blockIdx.x * blockDim.x + threadIdx.x;
    if (i >= n4) return;
    int col4 = (int)(i & (NF4 - 1));   // NF4 is power of two

    const float4* xp = reinterpret_cast<const float4*>(x);
    const float4* mp = reinterpret_cast<const float4*>(g_mean);
    const float4* sp = reinterpret_cast<const float4*>(g_istd);
    float4* op = reinterpret_cast<float4*>(out);

    float4 v = xp[i];
    float4 m = mp[col4];
    float4 s = sp[col4];
    float4 o;
    o.x = (v.x - m.x) * s.x;
    o.y = (v.y - m.y) * s.y;
    o.z = (v.z - m.z) * s.z;
    o.w = (v.w - m.w) * s.w;
    op[i] = o;
}

extern "C" void kernel_launch(void* const* d_in, const int* in_sizes, int n_in,
                              void* d_out, int out_size) {
    const float* x = (const float*)d_in[0];
    float* out = (float*)d_out;
    int rows = in_sizes[0] / NF;     // 8192

    // 1. zero accumulators
    zero_kernel<<<(NF + 255) / 256, 256>>>();

    // 2. column reduce: 2 column-blocks x 512 row-chunks (16 rows each) = 1024 CTAs
    int rowsPerChunk = 16;
    int chunks = (rows + rowsPerChunk - 1) / rowsPerChunk;
    dim3 rgrid(NF4 / 256, chunks);
    reduce_kernel<<<rgrid, 256>>>(x, rows, rowsPerChunk);

    // 3. stats
    stats_kernel<<<(NF + 255) / 256, 256>>>(rows);

    // 4. normalize
    size_t n4 = (size_t)rows * NF4;
    int nblocks = (int)((n4 + 255) / 256);
    normalize_kernel<<<nblocks, 256>>>(x, out, n4);
}

// round 3
// speedup vs baseline: 1.2897x; 1.2897x over previous
#include <cuda_runtime.h>
#include <cuda_bf16.h>

#define NF   2048
#define NF4  (NF / 4)      // 512 float4 per row
#define P    128           // row chunks
#define EPS  1e-6f

// Scratch (__device__ globals per allocation-free rule)
__device__ __align__(16) float g_ps[P * NF];   // partial sums   [p][c]
__device__ __align__(16) float g_pq[P * NF];   // partial sumsq  [p][c]
__device__ __align__(16) float g_mean[NF];
__device__ __align__(16) float g_istd[NF];

// grid (NF4/256, P), block 256. Thread owns 4 adjacent columns, rows/P rows.
// No atomics: writes its partial to g_ps/g_pq (coalesced float4 stores).
__global__ void reduce_kernel(const float* __restrict__ x, int rows) {
    int col4 = blockIdx.x * 256 + threadIdx.x;     // 0..NF4-1
    int p    = blockIdx.y;                          // 0..P-1
    int rpc  = rows / P;                            // rows per chunk (64)
    int r0   = p * rpc;

    const float4* xp = reinterpret_cast<const float4*>(x);

    float sx = 0.f, sy = 0.f, sz = 0.f, sw = 0.f;
    float qx = 0.f, qy = 0.f, qz = 0.f, qw = 0.f;

    #pragma unroll 1
    for (int r = 0; r < rpc; r += 4) {
        size_t base = (size_t)(r0 + r) * NF4 + col4;
        float4 v0 = xp[base];
        float4 v1 = xp[base + NF4];
        float4 v2 = xp[base + 2 * NF4];
        float4 v3 = xp[base + 3 * NF4];
        sx += v0.x; sy += v0.y; sz += v0.z; sw += v0.w;
        qx += v0.x * v0.x; qy += v0.y * v0.y; qz += v0.z * v0.z; qw += v0.w * v0.w;
        sx += v1.x; sy += v1.y; sz += v1.z; sw += v1.w;
        qx += v1.x * v1.x; qy += v1.y * v1.y; qz += v1.z * v1.z; qw += v1.w * v1.w;
        sx += v2.x; sy += v2.y; sz += v2.z; sw += v2.w;
        qx += v2.x * v2.x; qy += v2.y * v2.y; qz += v2.z * v2.z; qw += v2.w * v2.w;
        sx += v3.x; sy += v3.y; sz += v3.z; sw += v3.w;
        qx += v3.x * v3.x; qy += v3.y * v3.y; qz += v3.z * v3.z; qw += v3.w * v3.w;
    }

    float4* psp = reinterpret_cast<float4*>(g_ps);
    float4* pqp = reinterpret_cast<float4*>(g_pq);
    size_t o = (size_t)p * NF4 + col4;
    psp[o] = make_float4(sx, sy, sz, sw);
    pqp[o] = make_float4(qx, qy, qz, qw);
}

// One warp per col4 group (4 columns). Each lane sums P/32=4 partials
// (independent loads, L2-resident), then shfl butterfly across the warp.
__global__ void stats_kernel(int rows) {
    int gwarp = (blockIdx.x * blockDim.x + threadIdx.x) >> 5;  // 0..NF4-1
    int lane  = threadIdx.x & 31;
    if (gwarp >= NF4) return;

    const float4* psp = reinterpret_cast<const float4*>(g_ps);
    const float4* pqp = reinterpret_cast<const float4*>(g_pq);

    float4 s = make_float4(0.f, 0.f, 0.f, 0.f);
    float4 q = make_float4(0.f, 0.f, 0.f, 0.f);
    #pragma unroll
    for (int pp = 0; pp < P; pp += 32) {
        float4 a = psp[(size_t)(pp + lane) * NF4 + gwarp];
        float4 b = pqp[(size_t)(pp + lane) * NF4 + gwarp];
        s.x += a.x; s.y += a.y; s.z += a.z; s.w += a.w;
        q.x += b.x; q.y += b.y; q.z += b.z; q.w += b.w;
    }
    #pragma unroll
    for (int off = 16; off > 0; off >>= 1) {
        s.x += __shfl_xor_sync(0xffffffffu, s.x, off);
        s.y += __shfl_xor_sync(0xffffffffu, s.y, off);
        s.z += __shfl_xor_sync(0xffffffffu, s.z, off);
        s.w += __shfl_xor_sync(0xffffffffu, s.w, off);
        q.x += __shfl_xor_sync(0xffffffffu, q.x, off);
        q.y += __shfl_xor_sync(0xffffffffu, q.y, off);
        q.z += __shfl_xor_sync(0xffffffffu, q.z, off);
        q.w += __shfl_xor_sync(0xffffffffu, q.w, off);
    }
    if (lane == 0) {
        float n = (float)rows;
        float inv_n = 1.0f / n;
        float inv_n1 = 1.0f / (n - 1.0f);
        float4 m, is;
        m.x = s.x * inv_n; m.y = s.y * inv_n; m.z = s.z * inv_n; m.w = s.w * inv_n;
        is.x = rsqrtf((q.x - n * m.x * m.x) * inv_n1 + EPS);
        is.y = rsqrtf((q.y - n * m.y * m.y) * inv_n1 + EPS);
        is.z = rsqrtf((q.z - n * m.z * m.z) * inv_n1 + EPS);
        is.w = rsqrtf((q.w - n * m.w * m.w) * inv_n1 + EPS);
        reinterpret_cast<float4*>(g_mean)[gwarp] = m;
        reinterpret_cast<float4*>(g_istd)[gwarp] = is;
    }
}

// Each thread handles 4 float4s spaced by blockDim (independent loads, MLP=4).
// Block covers 1024 consecutive float4s (exactly 2 rows).
__global__ void normalize_kernel(const float* __restrict__ x,
                                 float* __restrict__ out, size_t n4) {
    size_t base = (size_t)blockIdx.x * 1024 + threadIdx.x;

    const float4* xp = reinterpret_cast<const float4*>(x);
    const float4* mp = reinterpret_cast<const float4*>(g_mean);
    const float4* sp = reinterpret_cast<const float4*>(g_istd);
    float4* op = reinterpret_cast<float4*>(out);

    size_t i0 = base, i1 = base + 256, i2 = base + 512, i3 = base + 768;
    if (i3 < n4) {
        float4 v0 = xp[i0], v1 = xp[i1], v2 = xp[i2], v3 = xp[i3];
        int c0 = (int)(i0 & (NF4 - 1)), c1 = (int)(i1 & (NF4 - 1));
        int c2 = (int)(i2 & (NF4 - 1)), c3 = (int)(i3 & (NF4 - 1));
        float4 m0 = mp[c0], m1 = mp[c1], m2 = mp[c2], m3 = mp[c3];
        float4 s0 = sp[c0], s1 = sp[c1], s2 = sp[c2], s3 = sp[c3];
        float4 o0, o1, o2, o3;
        o0.x = (v0.x - m0.x) * s0.x; o0.y = (v0.y - m0.y) * s0.y;
        o0.z = (v0.z - m0.z) * s0.z; o0.w = (v0.w - m0.w) * s0.w;
        o1.x = (v1.x - m1.x) * s1.x; o1.y = (v1.y - m1.y) * s1.y;
        o1.z = (v1.z - m1.z) * s1.z; o1.w = (v1.w - m1.w) * s1.w;
        o2.x = (v2.x - m2.x) * s2.x; o2.y = (v2.y - m2.y) * s2.y;
        o2.z = (v2.z - m2.z) * s2.z; o2.w = (v2.w - m2.w) * s2.w;
        o3.x = (v3.x - m3.x) * s3.x; o3.y = (v3.y - m3.y) * s3.y;
        o3.z = (v3.z - m3.z) * s3.z; o3.w = (v3.w - m3.w) * s3.w;
        op[i0] = o0; op[i1] = o1; op[i2] = o2; op[i3] = o3;
    } else {
        #pragma unroll
        for (int k = 0; k < 4; k++) {
            size_t i = base + (size_t)k * 256;
            if (i < n4) {
                float4 v = xp[i];
                int c = (int)(i & (NF4 - 1));
                float4 m = mp[c], s = sp[c];
                float4 o;
                o.x = (v.x - m.x) * s.x; o.y = (v.y - m.y) * s.y;
                o.z = (v.z - m.z) * s.z; o.w = (v.w - m.w) * s.w;
                op[i] = o;
            }
        }
    }
}

extern "C" void kernel_launch(void* const* d_in, const int* in_sizes, int n_in,
                              void* d_out, int out_size) {
    const float* x = (const float*)d_in[0];
    float* out = (float*)d_out;
    int rows = in_sizes[0] / NF;     // 8192

    // 1. atomic-free column reduce into [P][NF] partials
    dim3 rgrid(NF4 / 256, P);
    reduce_kernel<<<rgrid, 256>>>(x, rows);

    // 2. stats: one warp per 4 columns
    int swarps = NF4;                              // 512 warps
    stats_kernel<<<(swarps * 32 + 255) / 256, 256>>>(rows);

    // 3. normalize: 4 float4 per thread
    size_t n4 = (size_t)rows * NF4;
    int nblocks = (int)((n4 + 1023) / 1024);
    normalize_kernel<<<nblocks, 256>>>(x, out, n4);
}